// round 4
// baseline (speedup 1.0000x reference)
#include <cuda_runtime.h>
#include <math.h>
#include <stdint.h>

// Problem constants
#define TT    2048
#define DM    1024
#define DFF   2048
#define NH    4096
#define NE    16
#define NAg   4
#define NBg   4

// ---------------- device scratch ----------------
__device__ int   g_eidx[TT];
__device__ int   g_counts[NE];
__device__ int   g_offsets[NE + 1];
__device__ int   g_pos[NE];
__device__ int   g_perm[TT];
__device__ float g_probsum[NAg + NBg];
__device__ float g_ohsum[NAg + NBg];
__device__ float g_act[(size_t)TT * DFF];   // sorted activation rows (tf32-rounded)
__device__ float g_xr[(size_t)TT * DM];     // tf32-rounded copy of x

// ---------------- helpers ----------------
__device__ __forceinline__ uint32_t f2tf(float f) {
    uint32_t r;
    asm("cvt.rna.tf32.f32 %0, %1;" : "=r"(r) : "f"(f));
    return r;
}
__device__ __forceinline__ void mma_tf32(float c[4],
                                         const uint32_t a[4],
                                         const uint32_t b[2]) {
    asm volatile(
        "mma.sync.aligned.m16n8k8.row.col.f32.tf32.tf32.f32 "
        "{%0,%1,%2,%3}, {%4,%5,%6,%7}, {%8,%9}, {%0,%1,%2,%3};"
        : "+f"(c[0]), "+f"(c[1]), "+f"(c[2]), "+f"(c[3])
        : "r"(a[0]), "r"(a[1]), "r"(a[2]), "r"(a[3]), "r"(b[0]), "r"(b[1]));
}
__device__ __forceinline__ void cp16(uint32_t dst, const void* src, int src_bytes) {
    asm volatile("cp.async.cg.shared.global [%0], [%1], 16, %2;"
                 :: "r"(dst), "l"(src), "r"(src_bytes));
}
__device__ __forceinline__ void cp_commit() { asm volatile("cp.async.commit_group;"); }
__device__ __forceinline__ void cp_wait1()  { asm volatile("cp.async.wait_group 1;"); }
__device__ __forceinline__ void cp_wait0()  { asm volatile("cp.async.wait_group 0;"); }

// ---------------- small kernels ----------------
__global__ void zero_kernel() {
    int t = threadIdx.x;
    if (t < NE) g_counts[t] = 0;
    if (t < NAg + NBg) { g_probsum[t] = 0.f; g_ohsum[t] = 0.f; }
}

__global__ void round_x_kernel(const float* __restrict__ x) {
    int i = (blockIdx.x * blockDim.x + threadIdx.x) * 4;
    float4 v = *(const float4*)(x + i);
    float4 o;
    o.x = __uint_as_float(f2tf(v.x));
    o.y = __uint_as_float(f2tf(v.y));
    o.z = __uint_as_float(f2tf(v.z));
    o.w = __uint_as_float(f2tf(v.w));
    *(float4*)(g_xr + i) = o;
}

__global__ void gating_kernel(const float* __restrict__ x,
                              const float* __restrict__ Wga, const float* __restrict__ bga,
                              const float* __restrict__ Wgb, const float* __restrict__ bgb) {
    int warp = (blockIdx.x * blockDim.x + threadIdx.x) >> 5;
    int lane = threadIdx.x & 31;
    if (warp >= TT) return;
    const float* xr = x + (size_t)warp * DM;

    float acc[8];
#pragma unroll
    for (int j = 0; j < 8; j++) acc[j] = 0.f;
    for (int k = lane; k < DM; k += 32) {
        float xv = xr[k];
#pragma unroll
        for (int j = 0; j < 4; j++) acc[j]     += xv * Wga[k * 4 + j];
#pragma unroll
        for (int j = 0; j < 4; j++) acc[4 + j] += xv * Wgb[k * 4 + j];
    }
#pragma unroll
    for (int off = 16; off > 0; off >>= 1)
#pragma unroll
        for (int j = 0; j < 8; j++)
            acc[j] += __shfl_xor_sync(0xFFFFFFFFu, acc[j], off);

    if (lane == 0) {
        float la[4], lb[4];
#pragma unroll
        for (int j = 0; j < 4; j++) { la[j] = acc[j] + bga[j]; lb[j] = acc[4 + j] + bgb[j]; }
        float ma = la[0]; int ia = 0;
#pragma unroll
        for (int j = 1; j < 4; j++) if (la[j] > ma) { ma = la[j]; ia = j; }
        float mb = lb[0]; int ib = 0;
#pragma unroll
        for (int j = 1; j < 4; j++) if (lb[j] > mb) { mb = lb[j]; ib = j; }
        float pa[4], pb[4], sa = 0.f, sb = 0.f;
#pragma unroll
        for (int j = 0; j < 4; j++) { pa[j] = expf(la[j] - ma); sa += pa[j]; }
#pragma unroll
        for (int j = 0; j < 4; j++) { pb[j] = expf(lb[j] - mb); sb += pb[j]; }
        float rsa = 1.f / sa, rsb = 1.f / sb;
        int e = ia * NBg + ib;
        g_eidx[warp] = e;
        atomicAdd(&g_counts[e], 1);
#pragma unroll
        for (int j = 0; j < 4; j++) {
            atomicAdd(&g_probsum[j],     pa[j] * rsa);
            atomicAdd(&g_probsum[4 + j], pb[j] * rsb);
        }
        atomicAdd(&g_ohsum[ia], 1.f);
        atomicAdd(&g_ohsum[4 + ib], 1.f);
    }
}

__global__ void scan_kernel(float* __restrict__ out, int out_size) {
    if (threadIdx.x == 0) {
        int off = 0;
        for (int e = 0; e < NE; e++) {
            g_offsets[e] = off;
            g_pos[e] = off;
            off += g_counts[e];
        }
        g_offsets[NE] = off;
        if (out_size > TT * DM) {
            const float invT = 1.f / (float)TT;
            float auxA = 0.f, auxB = 0.f;
            for (int j = 0; j < 4; j++) auxA += (g_probsum[j]     * invT) * (g_ohsum[j]     * invT);
            for (int j = 0; j < 4; j++) auxB += (g_probsum[4 + j] * invT) * (g_ohsum[4 + j] * invT);
            out[TT * DM] = (float)NAg * auxA + (float)NBg * auxB;
        }
    }
}

__global__ void scatter_kernel() {
    int t = blockIdx.x * blockDim.x + threadIdx.x;
    if (t >= TT) return;
    int e = g_eidx[t];
    int p = atomicAdd(&g_pos[e], 1);
    g_perm[p] = t;
}

// out[t][:] = b2[e_idx[t]][:]  (bias pre-init for split-K atomic accumulation)
__global__ void init_out_kernel(const float* __restrict__ b2, float* __restrict__ out) {
    int idx = blockIdx.x * blockDim.x + threadIdx.x;       // one float4 per thread
    int t  = idx >> 8;                                     // DM/4 = 256 chunks per row
    int c4 = (idx & 255) * 4;
    int e = g_eidx[t];
    float4 bv = *(const float4*)(b2 + (size_t)e * DM + c4);
    *(float4*)(out + (size_t)t * DM + c4) = bv;
}

// =====================================================================
// Shared GEMM geometry: CTA 128(M) x 128(outputs), BK=32, 4 warps 2x2,
// warp tile 64x64, m16n8k8 tf32 mma (A operands pre-rounded -> no A cvt).
// smem: A[2][128][36] | B[2][32][136] | toks[128]
// A frag LDS banks: 4g+tg (conflict-free). B frag banks: 8tg+g (conflict-free).
// =====================================================================
#define A_STRIDE 36
#define B_STRIDE 136
#define SM_A_FLOATS (128 * A_STRIDE)           // 4608
#define SM_B_FLOATS (32 * B_STRIDE)            // 4352
#define SM_B_OFF    (2 * SM_A_FLOATS)          // floats
#define SM_TOK_OFF  (2 * SM_A_FLOATS + 2 * SM_B_FLOATS)
#define SM_TOTAL_BYTES ((SM_TOK_OFF + 128) * 4)   // 72192

// ---------------- GEMM1: x_sorted @ W1 (+b1) -> SwiGLU -> g_act ----------------
// CTA covers 64 a-cols + 64 g-cols, interleaved in smem 8-col groups:
// smem col c: p=c>>4, w=c&15;  w<8 -> a-col n0a+8p+w ; w>=8 -> g-col n0a+8p+(w-8)
__global__ __launch_bounds__(128, 2)
void gemm1_mma(const float* __restrict__ W1, const float* __restrict__ b1) {
    const int e = blockIdx.z;
    const int off  = g_offsets[e];
    const int cnt  = g_offsets[e + 1] - off;
    const int row0 = blockIdx.y * 128;
    if (row0 >= cnt) return;
    const int n0a = blockIdx.x * 64;
    const int rowsv = min(128, cnt - row0);

    extern __shared__ float sm[];
    float* Ab[2] = { sm, sm + SM_A_FLOATS };
    float* Bb[2] = { sm + SM_B_OFF, sm + SM_B_OFF + SM_B_FLOATS };

    const int tid = threadIdx.x;
    const int wid = tid >> 5, lane = tid & 31;
    const int g = lane >> 2, tg = lane & 3;
    const int wm = (wid >> 1) * 64;
    const int wn = (wid & 1) * 64;

    // A loader: thread tid -> tile row tid
    const int tok = (tid < rowsv) ? g_perm[off + row0 + tid] : -1;
    const float* arow = (tok >= 0) ? (g_xr + (size_t)tok * DM) : g_xr;
    const int ab = (tok >= 0) ? 16 : 0;
    uint32_t aA[2];
    aA[0] = (uint32_t)__cvta_generic_to_shared(&Ab[0][tid * A_STRIDE]);
    aA[1] = (uint32_t)__cvta_generic_to_shared(&Ab[1][tid * A_STRIDE]);

    // B loader: thread tid -> fixed col chunk, rows (tid>>5)+4j
    const int colc = (tid & 31) * 4;
    const int rowb = tid >> 5;
    const int pgrp = colc >> 4, wgrp = colc & 15;
    const int gcol = (wgrp < 8) ? (n0a + 8 * pgrp + wgrp)
                                : (DFF + n0a + 8 * pgrp + (wgrp - 8));
    const float* W1e = W1 + (size_t)e * DM * NH;
    uint32_t aB[2];
    aB[0] = (uint32_t)__cvta_generic_to_shared(&Bb[0][0]);
    aB[1] = (uint32_t)__cvta_generic_to_shared(&Bb[1][0]);

    auto issue = [&](int t, int s) {
        const int k0 = t * 32;
#pragma unroll
        for (int c = 0; c < 8; c++) cp16(aA[s] + c * 16, arow + k0 + c * 4, ab);
#pragma unroll
        for (int j = 0; j < 8; j++) {
            int r = rowb + 4 * j;
            cp16(aB[s] + (r * B_STRIDE + colc) * 4, W1e + (size_t)(k0 + r) * NH + gcol, 16);
        }
        cp_commit();
    };

    float c[4][8][4];
#pragma unroll
    for (int i = 0; i < 4; i++)
#pragma unroll
        for (int j = 0; j < 8; j++)
#pragma unroll
            for (int q = 0; q < 4; q++) c[i][j][q] = 0.f;

    const int NT = DM / 32;
    issue(0, 0);
    issue(1, 1);

    for (int t = 0; t < NT; t++) {
        const int s = t & 1;
        if (t + 1 < NT) cp_wait1(); else cp_wait0();
        __syncthreads();
        const float* As = Ab[s];
        const float* Bs = Bb[s];
#pragma unroll
        for (int kk = 0; kk < 32; kk += 8) {
            uint32_t ra[4][4];
#pragma unroll
            for (int mt = 0; mt < 4; mt++) {
                const float* p = As + (wm + mt * 16 + g) * A_STRIDE + kk + tg;
                ra[mt][0] = __float_as_uint(p[0]);
                ra[mt][1] = __float_as_uint(p[8 * A_STRIDE]);
                ra[mt][2] = __float_as_uint(p[4]);
                ra[mt][3] = __float_as_uint(p[8 * A_STRIDE + 4]);
            }
#pragma unroll
            for (int nt = 0; nt < 8; nt++) {
                const float* p = Bs + (kk + tg) * B_STRIDE + wn + 8 * nt + g;
                uint32_t rb[2];
                rb[0] = f2tf(p[0]);
                rb[1] = f2tf(p[4 * B_STRIDE]);
#pragma unroll
                for (int mt = 0; mt < 4; mt++) mma_tf32(c[mt][nt], ra[mt], rb);
            }
        }
        __syncthreads();
        if (t + 2 < NT) issue(t + 2, s);
    }

    // ---- epilogue: bias + a*silu(g), tf32-rounded -> g_act (sorted rows) ----
    const float* b1e = b1 + (size_t)e * NH;
    const int pbase = (wn >> 4);   // 0 or 4
#pragma unroll
    for (int mt = 0; mt < 4; mt++) {
#pragma unroll
        for (int q = 0; q < 4; q++) {
            const float* ca = c[mt][2 * q];
            const float* cg = c[mt][2 * q + 1];
            const int acol = n0a + 8 * (pbase + q) + 2 * tg;
            const float ba0 = b1e[acol],       ba1 = b1e[acol + 1];
            const float bg0 = b1e[DFF + acol], bg1 = b1e[DFF + acol + 1];
            const int r0 = wm + mt * 16 + g;
#pragma unroll
            for (int h = 0; h < 2; h++) {
                const int r = r0 + 8 * h;
                if (r < rowsv) {
                    float a0 = ca[2 * h] + ba0, a1 = ca[2 * h + 1] + ba1;
                    float g0 = cg[2 * h] + bg0, g1 = cg[2 * h + 1] + bg1;
                    float s0 = g0 / (1.f + expf(-g0));
                    float s1 = g1 / (1.f + expf(-g1));
                    float2 o = make_float2(__uint_as_float(f2tf(a0 * s0)),
                                           __uint_as_float(f2tf(a1 * s1)));
                    *(float2*)&g_act[(size_t)(off + row0 + r) * DFF + acol] = o;
                }
            }
        }
    }
}

// ---------------- GEMM2: act_sorted @ W2 -> atomicAdd into out (split-K x2) ----
__global__ __launch_bounds__(128, 2)
void gemm2_mma(const float* __restrict__ W2, float* __restrict__ out) {
    const int e     = blockIdx.z & 15;
    const int split = blockIdx.z >> 4;
    const int off  = g_offsets[e];
    const int cnt  = g_offsets[e + 1] - off;
    const int row0 = blockIdx.y * 128;
    if (row0 >= cnt) return;
    const int n0 = blockIdx.x * 128;
    const int rowsv = min(128, cnt - row0);
    const int kbase = split * (DFF / 2);

    extern __shared__ float sm[];
    float* Ab[2] = { sm, sm + SM_A_FLOATS };
    float* Bb[2] = { sm + SM_B_OFF, sm + SM_B_OFF + SM_B_FLOATS };
    int* toks = (int*)(sm + SM_TOK_OFF);

    const int tid = threadIdx.x;
    const int wid = tid >> 5, lane = tid & 31;
    const int g = lane >> 2, tg = lane & 3;
    const int wm = (wid >> 1) * 64;
    const int wn = (wid & 1) * 64;

    toks[tid] = (tid < rowsv) ? g_perm[off + row0 + tid] : -1;

    const bool avalid = (tid < rowsv);
    const float* arow = avalid ? (g_act + (size_t)(off + row0 + tid) * DFF + kbase) : g_act;
    const int ab = avalid ? 16 : 0;
    uint32_t aA[2];
    aA[0] = (uint32_t)__cvta_generic_to_shared(&Ab[0][tid * A_STRIDE]);
    aA[1] = (uint32_t)__cvta_generic_to_shared(&Ab[1][tid * A_STRIDE]);

    const int colc = (tid & 31) * 4;
    const int rowb = tid >> 5;
    const float* W2e = W2 + (size_t)e * DFF * DM + (size_t)kbase * DM + n0;
    uint32_t aB[2];
    aB[0] = (uint32_t)__cvta_generic_to_shared(&Bb[0][0]);
    aB[1] = (uint32_t)__cvta_generic_to_shared(&Bb[1][0]);

    auto issue = [&](int t, int s) {
        const int k0 = t * 32;
#pragma unroll
        for (int c = 0; c < 8; c++) cp16(aA[s] + c * 16, arow + k0 + c * 4, ab);
#pragma unroll
        for (int j = 0; j < 8; j++) {
            int r = rowb + 4 * j;
            cp16(aB[s] + (r * B_STRIDE + colc) * 4, W2e + (size_t)(k0 + r) * DM + colc, 16);
        }
        cp_commit();
    };

    float c[4][8][4];
#pragma unroll
    for (int i = 0; i < 4; i++)
#pragma unroll
        for (int j = 0; j < 8; j++)
#pragma unroll
            for (int q = 0; q < 4; q++) c[i][j][q] = 0.f;

    const int NT = (DFF / 2) / 32;
    issue(0, 0);
    issue(1, 1);

    for (int t = 0; t < NT; t++) {
        const int s = t & 1;
        if (t + 1 < NT) cp_wait1(); else cp_wait0();
        __syncthreads();
        const float* As = Ab[s];
        const float* Bs = Bb[s];
#pragma unroll
        for (int kk = 0; kk < 32; kk += 8) {
            uint32_t ra[4][4];
#pragma unroll
            for (int mt = 0; mt < 4; mt++) {
                const float* p = As + (wm + mt * 16 + g) * A_STRIDE + kk + tg;
                ra[mt][0] = __float_as_uint(p[0]);
                ra[mt][1] = __float_as_uint(p[8 * A_STRIDE]);
                ra[mt][2] = __float_as_uint(p[4]);
                ra[mt][3] = __float_as_uint(p[8 * A_STRIDE + 4]);
            }
#pragma unroll
            for (int nt = 0; nt < 8; nt++) {
                const float* p = Bs + (kk + tg) * B_STRIDE + wn + 8 * nt + g;
                uint32_t rb[2];
                rb[0] = f2tf(p[0]);
                rb[1] = f2tf(p[4 * B_STRIDE]);
#pragma unroll
                for (int mt = 0; mt < 4; mt++) mma_tf32(c[mt][nt], ra[mt], rb);
            }
        }
        __syncthreads();
        if (t + 2 < NT) issue(t + 2, s);
    }

    // ---- epilogue: atomic accumulate into out (bias pre-initialized) ----
#pragma unroll
    for (int mt = 0; mt < 4; mt++) {
        const int r0 = wm + mt * 16 + g;
#pragma unroll
        for (int h = 0; h < 2; h++) {
            const int r = r0 + 8 * h;
            if (r < rowsv) {
                const int tok = toks[r];
                float* drow = out + (size_t)tok * DM + n0 + wn;
#pragma unroll
                for (int nt = 0; nt < 8; nt++) {
                    atomicAdd(drow + 8 * nt + 2 * tg,     c[mt][nt][2 * h]);
                    atomicAdd(drow + 8 * nt + 2 * tg + 1, c[mt][nt][2 * h + 1]);
                }
            }
        }
    }
}

// ---------------- launch ----------------
extern "C" void kernel_launch(void* const* d_in, const int* in_sizes, int n_in,
                              void* d_out, int out_size) {
    const float* x   = (const float*)d_in[0];
    const float* W1  = (const float*)d_in[1];
    const float* b1  = (const float*)d_in[2];
    const float* W2  = (const float*)d_in[3];
    const float* b2  = (const float*)d_in[4];
    const float* Wga = (const float*)d_in[5];
    const float* bga = (const float*)d_in[6];
    const float* Wgb = (const float*)d_in[7];
    const float* bgb = (const float*)d_in[8];
    float* out = (float*)d_out;

    cudaFuncSetAttribute(gemm1_mma, cudaFuncAttributeMaxDynamicSharedMemorySize, SM_TOTAL_BYTES);
    cudaFuncSetAttribute(gemm2_mma, cudaFuncAttributeMaxDynamicSharedMemorySize, SM_TOTAL_BYTES);

    zero_kernel<<<1, 64>>>();
    gating_kernel<<<TT / 8, 256>>>(x, Wga, bga, Wgb, bgb);
    scan_kernel<<<1, 32>>>(out, out_size);
    scatter_kernel<<<TT / 256, 256>>>();
    round_x_kernel<<<TT * DM / 1024, 256>>>(x);
    init_out_kernel<<<TT * DM / 1024, 256>>>(b2, out);
    gemm1_mma<<<dim3(32, 16, NE), 128, SM_TOTAL_BYTES>>>(W1, b1);
    gemm2_mma<<<dim3(8, 16, NE * 2), 128, SM_TOTAL_BYTES>>>(W2, out);
}

// round 5
// speedup vs baseline: 1.3581x; 1.3581x over previous
#include <cuda_runtime.h>
#include <cuda_fp16.h>
#include <math.h>
#include <stdint.h>

// Problem constants
#define TT    2048
#define DM    1024
#define DFF   2048
#define NH    4096
#define NE    16
#define NAg   4
#define NBg   4

// ---------------- device scratch ----------------
__device__ int    g_eidx[TT];
__device__ int    g_counts[NE];
__device__ int    g_offsets[NE + 1];
__device__ int    g_pos[NE];
__device__ int    g_perm[TT];
__device__ float  g_probsum[NAg + NBg];
__device__ float  g_ohsum[NAg + NBg];
__device__ __half g_xh[(size_t)TT * DM];     // fp16 copy of x
__device__ __half g_acth[(size_t)TT * DFF];  // fp16 sorted activations

// ---------------- helpers ----------------
__device__ __forceinline__ void mma_f16(float c[4], const uint32_t a[4], const uint32_t b[2]) {
    asm volatile(
        "mma.sync.aligned.m16n8k16.row.col.f32.f16.f16.f32 "
        "{%0,%1,%2,%3}, {%4,%5,%6,%7}, {%8,%9}, {%0,%1,%2,%3};"
        : "+f"(c[0]), "+f"(c[1]), "+f"(c[2]), "+f"(c[3])
        : "r"(a[0]), "r"(a[1]), "r"(a[2]), "r"(a[3]), "r"(b[0]), "r"(b[1]));
}
__device__ __forceinline__ void ldm_x4(uint32_t r[4], uint32_t addr) {
    asm volatile("ldmatrix.sync.aligned.m8n8.x4.shared.b16 {%0,%1,%2,%3}, [%4];"
                 : "=r"(r[0]), "=r"(r[1]), "=r"(r[2]), "=r"(r[3]) : "r"(addr));
}
__device__ __forceinline__ uint32_t pack_h2(float lo, float hi) {
    __half2 h = __floats2half2_rn(lo, hi);
    return *(uint32_t*)&h;
}
__device__ __forceinline__ void cp16(uint32_t dst, const void* src, int src_bytes) {
    asm volatile("cp.async.cg.shared.global [%0], [%1], 16, %2;"
                 :: "r"(dst), "l"(src), "r"(src_bytes));
}
__device__ __forceinline__ void cp_commit() { asm volatile("cp.async.commit_group;"); }
__device__ __forceinline__ void cp_wait1()  { asm volatile("cp.async.wait_group 1;"); }
__device__ __forceinline__ void cp_wait0()  { asm volatile("cp.async.wait_group 0;"); }

// ---------------- small kernels ----------------
__global__ void zero_kernel() {
    int t = threadIdx.x;
    if (t < NE) g_counts[t] = 0;
    if (t < NAg + NBg) { g_probsum[t] = 0.f; g_ohsum[t] = 0.f; }
}

__global__ void cvt_x_kernel(const float* __restrict__ x) {
    int i = (blockIdx.x * blockDim.x + threadIdx.x) * 4;
    float4 v = *(const float4*)(x + i);
    __half2* dst = (__half2*)(g_xh + i);
    dst[0] = __floats2half2_rn(v.x, v.y);
    dst[1] = __floats2half2_rn(v.z, v.w);
}

__global__ void gating_kernel(const float* __restrict__ x,
                              const float* __restrict__ Wga, const float* __restrict__ bga,
                              const float* __restrict__ Wgb, const float* __restrict__ bgb) {
    int warp = (blockIdx.x * blockDim.x + threadIdx.x) >> 5;
    int lane = threadIdx.x & 31;
    if (warp >= TT) return;
    const float* xr = x + (size_t)warp * DM;

    float acc[8];
#pragma unroll
    for (int j = 0; j < 8; j++) acc[j] = 0.f;
    for (int k = lane; k < DM; k += 32) {
        float xv = xr[k];
#pragma unroll
        for (int j = 0; j < 4; j++) acc[j]     += xv * Wga[k * 4 + j];
#pragma unroll
        for (int j = 0; j < 4; j++) acc[4 + j] += xv * Wgb[k * 4 + j];
    }
#pragma unroll
    for (int off = 16; off > 0; off >>= 1)
#pragma unroll
        for (int j = 0; j < 8; j++)
            acc[j] += __shfl_xor_sync(0xFFFFFFFFu, acc[j], off);

    if (lane == 0) {
        float la[4], lb[4];
#pragma unroll
        for (int j = 0; j < 4; j++) { la[j] = acc[j] + bga[j]; lb[j] = acc[4 + j] + bgb[j]; }
        float ma = la[0]; int ia = 0;
#pragma unroll
        for (int j = 1; j < 4; j++) if (la[j] > ma) { ma = la[j]; ia = j; }
        float mb = lb[0]; int ib = 0;
#pragma unroll
        for (int j = 1; j < 4; j++) if (lb[j] > mb) { mb = lb[j]; ib = j; }
        float pa[4], pb[4], sa = 0.f, sb = 0.f;
#pragma unroll
        for (int j = 0; j < 4; j++) { pa[j] = expf(la[j] - ma); sa += pa[j]; }
#pragma unroll
        for (int j = 0; j < 4; j++) { pb[j] = expf(lb[j] - mb); sb += pb[j]; }
        float rsa = 1.f / sa, rsb = 1.f / sb;
        int e = ia * NBg + ib;
        g_eidx[warp] = e;
        atomicAdd(&g_counts[e], 1);
#pragma unroll
        for (int j = 0; j < 4; j++) {
            atomicAdd(&g_probsum[j],     pa[j] * rsa);
            atomicAdd(&g_probsum[4 + j], pb[j] * rsb);
        }
        atomicAdd(&g_ohsum[ia], 1.f);
        atomicAdd(&g_ohsum[4 + ib], 1.f);
    }
}

__global__ void scan_kernel(float* __restrict__ out, int out_size) {
    if (threadIdx.x == 0) {
        int off = 0;
        for (int e = 0; e < NE; e++) {
            g_offsets[e] = off;
            g_pos[e] = off;
            off += g_counts[e];
        }
        g_offsets[NE] = off;
        if (out_size > TT * DM) {
            const float invT = 1.f / (float)TT;
            float auxA = 0.f, auxB = 0.f;
            for (int j = 0; j < 4; j++) auxA += (g_probsum[j]     * invT) * (g_ohsum[j]     * invT);
            for (int j = 0; j < 4; j++) auxB += (g_probsum[4 + j] * invT) * (g_ohsum[4 + j] * invT);
            out[TT * DM] = (float)NAg * auxA + (float)NBg * auxB;
        }
    }
}

__global__ void scatter_kernel() {
    int t = blockIdx.x * blockDim.x + threadIdx.x;
    if (t >= TT) return;
    int e = g_eidx[t];
    int p = atomicAdd(&g_pos[e], 1);
    g_perm[p] = t;
}

// out[t][:] = b2[e_idx[t]][:]  (bias pre-init for split-K atomic accumulation)
__global__ void init_out_kernel(const float* __restrict__ b2, float* __restrict__ out) {
    int idx = blockIdx.x * blockDim.x + threadIdx.x;
    int t  = idx >> 8;
    int c4 = (idx & 255) * 4;
    int e = g_eidx[t];
    float4 bv = *(const float4*)(b2 + (size_t)e * DM + c4);
    *(float4*)(out + (size_t)t * DM + c4) = bv;
}

// =====================================================================
// GEMM geometry: CTA 128(M) x 128(outputs), BK=32, 4 warps 2x2,
// warp tile 64x64, m16n8k16 fp16 mma, fp32 accum.
// A: fp16 smem, stride 40 halves (ldmatrix conflict-free).
// B: fp32 smem, stride 140 floats (k16 fragment LDS conflict-free),
//    converted to f16x2 at fragment-load time.
// smem bytes: A0[0,10240) A1[10240,20480) B0[20480,38400) B1[38400,56320)
//             toks @56320. total 56832.
// =====================================================================
#define AH_STRIDE 40
#define BF_STRIDE 140
#define SMH_A_BYTES 10240
#define SMH_B_BYTES 17920
#define SM_B_BASE   20480
#define SM_TOK_BASE 56320
#define SM_TOTAL_BYTES 56832

// ---------------- GEMM1: x_sorted(fp16) @ W1 (+b1) -> SwiGLU -> g_acth ----------------
// CTA covers 64 a-cols + 64 g-cols interleaved in 8-col groups.
__global__ __launch_bounds__(128, 2)
void gemm1_mma(const float* __restrict__ W1, const float* __restrict__ b1) {
    const int e = blockIdx.z;
    const int off  = g_offsets[e];
    const int cnt  = g_offsets[e + 1] - off;
    const int row0 = blockIdx.y * 128;
    if (row0 >= cnt) return;
    const int n0a = blockIdx.x * 64;
    const int rowsv = min(128, cnt - row0);

    extern __shared__ char sm[];
    __half* AbH = (__half*)sm;
    float*  Bb  = (float*)(sm + SM_B_BASE);

    const int tid = threadIdx.x;
    const int wid = tid >> 5, lane = tid & 31;
    const int g = lane >> 2, tg = lane & 3;
    const int wm = (wid >> 1) * 64;
    const int wn = (wid & 1) * 64;

    // A loader: thread tid -> tile row tid (64B per buffer)
    const int tok = (tid < rowsv) ? g_perm[off + row0 + tid] : -1;
    const __half* arow = (tok >= 0) ? (g_xh + (size_t)tok * DM) : g_xh;
    const int ab = (tok >= 0) ? 16 : 0;
    const uint32_t aAbase = (uint32_t)__cvta_generic_to_shared(AbH) + tid * (AH_STRIDE * 2);

    // B loader: fixed col chunk, rows (tid>>5)+4j
    const int colc = (tid & 31) * 4;
    const int rowb = tid >> 5;
    const int pgrp = colc >> 4, wgrp = colc & 15;
    const int gcol = (wgrp < 8) ? (n0a + 8 * pgrp + wgrp)
                                : (DFF + n0a + 8 * pgrp + (wgrp - 8));
    const float* W1e = W1 + (size_t)e * DM * NH;
    const uint32_t aBbase = (uint32_t)__cvta_generic_to_shared(Bb);

    auto issue = [&](int t, int s) {
        const int k0 = t * 32;
        const uint32_t aA = aAbase + s * SMH_A_BYTES;
#pragma unroll
        for (int c = 0; c < 4; c++) cp16(aA + c * 16, arow + k0 + c * 8, ab);
        const uint32_t aB = aBbase + s * SMH_B_BYTES;
#pragma unroll
        for (int j = 0; j < 8; j++) {
            int r = rowb + 4 * j;
            cp16(aB + (r * BF_STRIDE + colc) * 4, W1e + (size_t)(k0 + r) * NH + gcol, 16);
        }
        cp_commit();
    };

    // ldmatrix per-thread base: row = wm + (lane&15), k-half offset (lane>>4)*8
    const uint32_t ldmBase = (uint32_t)__cvta_generic_to_shared(AbH) +
        (((wm + (lane & 15)) * AH_STRIDE + ((lane >> 4) * 8)) * 2);

    float c[4][8][4];
#pragma unroll
    for (int i = 0; i < 4; i++)
#pragma unroll
        for (int j = 0; j < 8; j++)
#pragma unroll
            for (int q = 0; q < 4; q++) c[i][j][q] = 0.f;

    const int NT = DM / 32;
    issue(0, 0);
    issue(1, 1);

    for (int t = 0; t < NT; t++) {
        const int s = t & 1;
        if (t + 1 < NT) cp_wait1(); else cp_wait0();
        __syncthreads();
        const float* Bs = Bb + s * (SMH_B_BYTES / 4);
        const uint32_t aldm = ldmBase + s * SMH_A_BYTES;
#pragma unroll
        for (int kk = 0; kk < 32; kk += 16) {
            uint32_t ra[4][4];
#pragma unroll
            for (int mt = 0; mt < 4; mt++)
                ldm_x4(ra[mt], aldm + (mt * 16 * AH_STRIDE + kk) * 2);
#pragma unroll
            for (int nt = 0; nt < 8; nt++) {
                const float* p = Bs + (kk + 2 * tg) * BF_STRIDE + wn + 8 * nt + g;
                uint32_t rb[2];
                rb[0] = pack_h2(p[0],             p[BF_STRIDE]);
                rb[1] = pack_h2(p[8 * BF_STRIDE], p[9 * BF_STRIDE]);
#pragma unroll
                for (int mt = 0; mt < 4; mt++) mma_f16(c[mt][nt], ra[mt], rb);
            }
        }
        __syncthreads();
        if (t + 2 < NT) issue(t + 2, s);
    }

    // ---- epilogue: bias + a*silu(g) -> g_acth (fp16, sorted rows) ----
    const float* b1e = b1 + (size_t)e * NH;
    const int pbase = (wn >> 4);
#pragma unroll
    for (int mt = 0; mt < 4; mt++) {
#pragma unroll
        for (int q = 0; q < 4; q++) {
            const float* ca = c[mt][2 * q];
            const float* cg = c[mt][2 * q + 1];
            const int acol = n0a + 8 * (pbase + q) + 2 * tg;
            const float ba0 = b1e[acol],       ba1 = b1e[acol + 1];
            const float bg0 = b1e[DFF + acol], bg1 = b1e[DFF + acol + 1];
            const int r0 = wm + mt * 16 + g;
#pragma unroll
            for (int h = 0; h < 2; h++) {
                const int r = r0 + 8 * h;
                if (r < rowsv) {
                    float a0 = ca[2 * h] + ba0, a1 = ca[2 * h + 1] + ba1;
                    float g0 = cg[2 * h] + bg0, g1 = cg[2 * h + 1] + bg1;
                    float s0 = g0 / (1.f + expf(-g0));
                    float s1 = g1 / (1.f + expf(-g1));
                    *(__half2*)&g_acth[(size_t)(off + row0 + r) * DFF + acol] =
                        __floats2half2_rn(a0 * s0, a1 * s1);
                }
            }
        }
    }
}

// ---------------- GEMM2: act_sorted(fp16) @ W2 -> atomicAdd into out (split-K x2) ----
__global__ __launch_bounds__(128, 2)
void gemm2_mma(const float* __restrict__ W2, float* __restrict__ out) {
    const int e     = blockIdx.z & 15;
    const int split = blockIdx.z >> 4;
    const int off  = g_offsets[e];
    const int cnt  = g_offsets[e + 1] - off;
    const int row0 = blockIdx.y * 128;
    if (row0 >= cnt) return;
    const int n0 = blockIdx.x * 128;
    const int rowsv = min(128, cnt - row0);
    const int kbase = split * (DFF / 2);

    extern __shared__ char sm[];
    __half* AbH = (__half*)sm;
    float*  Bb  = (float*)(sm + SM_B_BASE);
    int*    toks = (int*)(sm + SM_TOK_BASE);

    const int tid = threadIdx.x;
    const int wid = tid >> 5, lane = tid & 31;
    const int g = lane >> 2, tg = lane & 3;
    const int wm = (wid >> 1) * 64;
    const int wn = (wid & 1) * 64;

    toks[tid] = (tid < rowsv) ? g_perm[off + row0 + tid] : -1;

    const bool avalid = (tid < rowsv);
    const __half* arow = avalid ? (g_acth + (size_t)(off + row0 + tid) * DFF + kbase) : g_acth;
    const int ab = avalid ? 16 : 0;
    const uint32_t aAbase = (uint32_t)__cvta_generic_to_shared(AbH) + tid * (AH_STRIDE * 2);

    const int colc = (tid & 31) * 4;
    const int rowb = tid >> 5;
    const float* W2e = W2 + (size_t)e * DFF * DM + (size_t)kbase * DM + n0;
    const uint32_t aBbase = (uint32_t)__cvta_generic_to_shared(Bb);

    auto issue = [&](int t, int s) {
        const int k0 = t * 32;
        const uint32_t aA = aAbase + s * SMH_A_BYTES;
#pragma unroll
        for (int c = 0; c < 4; c++) cp16(aA + c * 16, arow + k0 + c * 8, ab);
        const uint32_t aB = aBbase + s * SMH_B_BYTES;
#pragma unroll
        for (int j = 0; j < 8; j++) {
            int r = rowb + 4 * j;
            cp16(aB + (r * BF_STRIDE + colc) * 4, W2e + (size_t)(k0 + r) * DM + colc, 16);
        }
        cp_commit();
    };

    const uint32_t ldmBase = (uint32_t)__cvta_generic_to_shared(AbH) +
        (((wm + (lane & 15)) * AH_STRIDE + ((lane >> 4) * 8)) * 2);

    float c[4][8][4];
#pragma unroll
    for (int i = 0; i < 4; i++)
#pragma unroll
        for (int j = 0; j < 8; j++)
#pragma unroll
            for (int q = 0; q < 4; q++) c[i][j][q] = 0.f;

    const int NT = (DFF / 2) / 32;
    issue(0, 0);
    issue(1, 1);

    for (int t = 0; t < NT; t++) {
        const int s = t & 1;
        if (t + 1 < NT) cp_wait1(); else cp_wait0();
        __syncthreads();
        const float* Bs = Bb + s * (SMH_B_BYTES / 4);
        const uint32_t aldm = ldmBase + s * SMH_A_BYTES;
#pragma unroll
        for (int kk = 0; kk < 32; kk += 16) {
            uint32_t ra[4][4];
#pragma unroll
            for (int mt = 0; mt < 4; mt++)
                ldm_x4(ra[mt], aldm + (mt * 16 * AH_STRIDE + kk) * 2);
#pragma unroll
            for (int nt = 0; nt < 8; nt++) {
                const float* p = Bs + (kk + 2 * tg) * BF_STRIDE + wn + 8 * nt + g;
                uint32_t rb[2];
                rb[0] = pack_h2(p[0],             p[BF_STRIDE]);
                rb[1] = pack_h2(p[8 * BF_STRIDE], p[9 * BF_STRIDE]);
#pragma unroll
                for (int mt = 0; mt < 4; mt++) mma_f16(c[mt][nt], ra[mt], rb);
            }
        }
        __syncthreads();
        if (t + 2 < NT) issue(t + 2, s);
    }

    // ---- epilogue: atomic accumulate into out (bias pre-initialized) ----
#pragma unroll
    for (int mt = 0; mt < 4; mt++) {
        const int r0 = wm + mt * 16 + g;
#pragma unroll
        for (int h = 0; h < 2; h++) {
            const int r = r0 + 8 * h;
            if (r < rowsv) {
                const int tok = toks[r];
                float* drow = out + (size_t)tok * DM + n0 + wn;
#pragma unroll
                for (int nt = 0; nt < 8; nt++) {
                    atomicAdd(drow + 8 * nt + 2 * tg,     c[mt][nt][2 * h]);
                    atomicAdd(drow + 8 * nt + 2 * tg + 1, c[mt][nt][2 * h + 1]);
                }
            }
        }
    }
}

// ---------------- launch ----------------
extern "C" void kernel_launch(void* const* d_in, const int* in_sizes, int n_in,
                              void* d_out, int out_size) {
    const float* x   = (const float*)d_in[0];
    const float* W1  = (const float*)d_in[1];
    const float* b1  = (const float*)d_in[2];
    const float* W2  = (const float*)d_in[3];
    const float* b2  = (const float*)d_in[4];
    const float* Wga = (const float*)d_in[5];
    const float* bga = (const float*)d_in[6];
    const float* Wgb = (const float*)d_in[7];
    const float* bgb = (const float*)d_in[8];
    float* out = (float*)d_out;

    cudaFuncSetAttribute(gemm1_mma, cudaFuncAttributeMaxDynamicSharedMemorySize, SM_TOTAL_BYTES);
    cudaFuncSetAttribute(gemm2_mma, cudaFuncAttributeMaxDynamicSharedMemorySize, SM_TOTAL_BYTES);

    zero_kernel<<<1, 64>>>();
    gating_kernel<<<TT / 8, 256>>>(x, Wga, bga, Wgb, bgb);
    scan_kernel<<<1, 32>>>(out, out_size);
    scatter_kernel<<<TT / 256, 256>>>();
    cvt_x_kernel<<<TT * DM / 1024, 256>>>(x);
    init_out_kernel<<<TT * DM / 1024, 256>>>(b2, out);
    gemm1_mma<<<dim3(32, 16, NE), 128, SM_TOTAL_BYTES>>>(W1, b1);
    gemm2_mma<<<dim3(8, 16, NE * 2), 128, SM_TOTAL_BYTES>>>(W2, out);
}

// round 6
// speedup vs baseline: 1.6944x; 1.2476x over previous
#include <cuda_runtime.h>
#include <cuda_fp16.h>
#include <math.h>
#include <stdint.h>

// Problem constants
#define TT    2048
#define DM    1024
#define DFF   2048
#define NH    4096
#define NE    16
#define NAg   4
#define NBg   4

// ---------------- device scratch ----------------
__device__ int    g_eidx[TT];
__device__ int    g_counts[NE];
__device__ int    g_offsets[NE + 1];
__device__ int    g_pos[NE];
__device__ int    g_perm[TT];
__device__ float  g_probsum[NAg + NBg];
__device__ float  g_ohsum[NAg + NBg];
__device__ __half g_xh[(size_t)TT * DM];     // fp16 copy of x
__device__ __half g_acth[(size_t)TT * DFF];  // fp16 sorted activations

// ---------------- helpers ----------------
__device__ __forceinline__ void mma_f16(float c[4], const uint32_t a[4], const uint32_t b[2]) {
    asm volatile(
        "mma.sync.aligned.m16n8k16.row.col.f32.f16.f16.f32 "
        "{%0,%1,%2,%3}, {%4,%5,%6,%7}, {%8,%9}, {%0,%1,%2,%3};"
        : "+f"(c[0]), "+f"(c[1]), "+f"(c[2]), "+f"(c[3])
        : "r"(a[0]), "r"(a[1]), "r"(a[2]), "r"(a[3]), "r"(b[0]), "r"(b[1]));
}
__device__ __forceinline__ void ldm_x4(uint32_t r[4], uint32_t addr) {
    asm volatile("ldmatrix.sync.aligned.m8n8.x4.shared.b16 {%0,%1,%2,%3}, [%4];"
                 : "=r"(r[0]), "=r"(r[1]), "=r"(r[2]), "=r"(r[3]) : "r"(addr));
}
__device__ __forceinline__ void ldm_x4_t(uint32_t r[4], uint32_t addr) {
    asm volatile("ldmatrix.sync.aligned.m8n8.x4.trans.shared.b16 {%0,%1,%2,%3}, [%4];"
                 : "=r"(r[0]), "=r"(r[1]), "=r"(r[2]), "=r"(r[3]) : "r"(addr));
}
__device__ __forceinline__ uint32_t pack_h2(float lo, float hi) {
    __half2 h = __floats2half2_rn(lo, hi);
    return *(uint32_t*)&h;
}
__device__ __forceinline__ void sts64(uint32_t addr, uint32_t v0, uint32_t v1) {
    asm volatile("st.shared.v2.u32 [%0], {%1,%2};" :: "r"(addr), "r"(v0), "r"(v1) : "memory");
}
__device__ __forceinline__ void cp16(uint32_t dst, const void* src, int src_bytes) {
    asm volatile("cp.async.cg.shared.global [%0], [%1], 16, %2;"
                 :: "r"(dst), "l"(src), "r"(src_bytes));
}
__device__ __forceinline__ void cp_commit() { asm volatile("cp.async.commit_group;"); }
__device__ __forceinline__ void cp_wait1()  { asm volatile("cp.async.wait_group 1;"); }

// ---------------- small kernels ----------------
__global__ void zero_kernel() {
    int t = threadIdx.x;
    if (t < NE) g_counts[t] = 0;
    if (t < NAg + NBg) { g_probsum[t] = 0.f; g_ohsum[t] = 0.f; }
}

__global__ void cvt_x_kernel(const float* __restrict__ x) {
    int i = (blockIdx.x * blockDim.x + threadIdx.x) * 4;
    float4 v = *(const float4*)(x + i);
    __half2* dst = (__half2*)(g_xh + i);
    dst[0] = __floats2half2_rn(v.x, v.y);
    dst[1] = __floats2half2_rn(v.z, v.w);
}

__global__ void gating_kernel(const float* __restrict__ x,
                              const float* __restrict__ Wga, const float* __restrict__ bga,
                              const float* __restrict__ Wgb, const float* __restrict__ bgb) {
    int warp = (blockIdx.x * blockDim.x + threadIdx.x) >> 5;
    int lane = threadIdx.x & 31;
    if (warp >= TT) return;
    const float* xr = x + (size_t)warp * DM;

    float acc[8];
#pragma unroll
    for (int j = 0; j < 8; j++) acc[j] = 0.f;
    for (int k = lane; k < DM; k += 32) {
        float xv = xr[k];
#pragma unroll
        for (int j = 0; j < 4; j++) acc[j]     += xv * Wga[k * 4 + j];
#pragma unroll
        for (int j = 0; j < 4; j++) acc[4 + j] += xv * Wgb[k * 4 + j];
    }
#pragma unroll
    for (int off = 16; off > 0; off >>= 1)
#pragma unroll
        for (int j = 0; j < 8; j++)
            acc[j] += __shfl_xor_sync(0xFFFFFFFFu, acc[j], off);

    if (lane == 0) {
        float la[4], lb[4];
#pragma unroll
        for (int j = 0; j < 4; j++) { la[j] = acc[j] + bga[j]; lb[j] = acc[4 + j] + bgb[j]; }
        float ma = la[0]; int ia = 0;
#pragma unroll
        for (int j = 1; j < 4; j++) if (la[j] > ma) { ma = la[j]; ia = j; }
        float mb = lb[0]; int ib = 0;
#pragma unroll
        for (int j = 1; j < 4; j++) if (lb[j] > mb) { mb = lb[j]; ib = j; }
        float pa[4], pb[4], sa = 0.f, sb = 0.f;
#pragma unroll
        for (int j = 0; j < 4; j++) { pa[j] = expf(la[j] - ma); sa += pa[j]; }
#pragma unroll
        for (int j = 0; j < 4; j++) { pb[j] = expf(lb[j] - mb); sb += pb[j]; }
        float rsa = 1.f / sa, rsb = 1.f / sb;
        int e = ia * NBg + ib;
        g_eidx[warp] = e;
        atomicAdd(&g_counts[e], 1);
#pragma unroll
        for (int j = 0; j < 4; j++) {
            atomicAdd(&g_probsum[j],     pa[j] * rsa);
            atomicAdd(&g_probsum[4 + j], pb[j] * rsb);
        }
        atomicAdd(&g_ohsum[ia], 1.f);
        atomicAdd(&g_ohsum[4 + ib], 1.f);
    }
}

__global__ void scan_kernel(float* __restrict__ out, int out_size) {
    if (threadIdx.x == 0) {
        int off = 0;
        for (int e = 0; e < NE; e++) {
            g_offsets[e] = off;
            g_pos[e] = off;
            off += g_counts[e];
        }
        g_offsets[NE] = off;
        if (out_size > TT * DM) {
            const float invT = 1.f / (float)TT;
            float auxA = 0.f, auxB = 0.f;
            for (int j = 0; j < 4; j++) auxA += (g_probsum[j]     * invT) * (g_ohsum[j]     * invT);
            for (int j = 0; j < 4; j++) auxB += (g_probsum[4 + j] * invT) * (g_ohsum[4 + j] * invT);
            out[TT * DM] = (float)NAg * auxA + (float)NBg * auxB;
        }
    }
}

__global__ void scatter_kernel() {
    int t = blockIdx.x * blockDim.x + threadIdx.x;
    if (t >= TT) return;
    int e = g_eidx[t];
    int p = atomicAdd(&g_pos[e], 1);
    g_perm[p] = t;
}

// out[t][:] = b2[e_idx[t]][:]  (bias pre-init for split-K atomic accumulation)
__global__ void init_out_kernel(const float* __restrict__ b2, float* __restrict__ out) {
    int idx = blockIdx.x * blockDim.x + threadIdx.x;
    int t  = idx >> 8;
    int c4 = (idx & 255) * 4;
    int e = g_eidx[t];
    float4 bv = *(const float4*)(b2 + (size_t)e * DM + c4);
    *(float4*)(out + (size_t)t * DM + c4) = bv;
}

// =====================================================================
// GEMM geometry: CTA 128(M) x 128(outputs), BK=32, 8 warps (2M x 4N),
// warp tile 64x32, m16n8k16 fp16 HMMA, fp32 accum.
// A: fp16 smem, stride 40 halves (ldmatrix conflict-free), cp.async.
// B: fp16 smem, stride 136 halves (trans-ldmatrix conflict-free),
//    LDG.128 fp32 -> F2FP.PACK -> STS.64, register-staged 2 tiles ahead.
// smem: A[2]@0 (2x10240) | B[2]@20480 (2x8704) | toks@37888. total 38400 B.
// =====================================================================
#define ASTR_H 40
#define BSTR_H 136
#define A_BUF_BYTES 10240
#define B_BUF_BYTES 8704
#define SM_B_BASE   20480
#define SM_TOK_BASE 37888
#define SM_TOTAL    38400

// ---------------- GEMM1: x_sorted(fp16) @ W1 (+b1) -> SwiGLU -> g_acth ----------------
// CTA covers 64 a-cols + 64 g-cols interleaved in 8-col groups.
__global__ __launch_bounds__(256, 2)
void gemm1_mma(const float* __restrict__ W1, const float* __restrict__ b1) {
    const int e = blockIdx.z;
    const int off  = g_offsets[e];
    const int cnt  = g_offsets[e + 1] - off;
    const int row0 = blockIdx.y * 128;
    if (row0 >= cnt) return;
    const int n0a = blockIdx.x * 64;
    const int rowsv = min(128, cnt - row0);

    extern __shared__ char sm[];
    const uint32_t smb = (uint32_t)__cvta_generic_to_shared(sm);

    const int tid = threadIdx.x;
    const int wid = tid >> 5, lane = tid & 31;
    const int g = lane >> 2, tg = lane & 3;
    const int wm = (wid >> 2) * 64;
    const int wn = (wid & 3) * 32;

    // A loader: 2 threads per row, 32B each
    const int arow_i = tid >> 1, ahalf = tid & 1;
    const int atok = (arow_i < rowsv) ? g_perm[off + row0 + arow_i] : -1;
    const __half* arow = (atok >= 0) ? (g_xh + (size_t)atok * DM) : g_xh;
    const int ab = (atok >= 0) ? 16 : 0;
    const uint32_t aA = smb + (arow_i * ASTR_H + ahalf * 16) * 2;

    // B loader: fp32 LDG, fp16 STS
    const int colc = (tid & 31) * 4;
    const int rowb = tid >> 5;                    // 0..7, rows rowb+8j
    const int pgrp = colc >> 4, wgrp = colc & 15;
    const int gcol = (wgrp < 8) ? (n0a + 8 * pgrp + wgrp)
                                : (DFF + n0a + 8 * pgrp + (wgrp - 8));
    const float* W1e = W1 + (size_t)e * DM * NH;
    const uint32_t aB = smb + SM_B_BASE + (rowb * BSTR_H + colc) * 2;

    float bre[16];
    auto ldB = [&](int t) {
        const int k0 = t * 32;
#pragma unroll
        for (int j = 0; j < 4; j++) {
            float4 v = *(const float4*)(W1e + (size_t)(k0 + rowb + 8 * j) * NH + gcol);
            bre[4 * j] = v.x; bre[4 * j + 1] = v.y; bre[4 * j + 2] = v.z; bre[4 * j + 3] = v.w;
        }
    };
    auto stsB = [&](int s) {
        const uint32_t base = aB + s * B_BUF_BYTES;
#pragma unroll
        for (int j = 0; j < 4; j++)
            sts64(base + (8 * j * BSTR_H) * 2,
                  pack_h2(bre[4 * j], bre[4 * j + 1]),
                  pack_h2(bre[4 * j + 2], bre[4 * j + 3]));
    };
    auto issueA = [&](int t, int s) {
        const int k0 = t * 32 + ahalf * 16;
        cp16(aA + s * A_BUF_BYTES,      arow + k0,     ab);
        cp16(aA + s * A_BUF_BYTES + 16, arow + k0 + 8, ab);
        cp_commit();
    };

    // ldmatrix bases
    const uint32_t aldmA = smb + ((wm + (lane & 15)) * ASTR_H + (lane >> 4) * 8) * 2;
    const int btr = (lane & 7) + 8 * ((lane >> 3) & 1);
    const int btc = 8 * (lane >> 4);
    const uint32_t aldmB = smb + SM_B_BASE + (btr * BSTR_H + wn + btc) * 2;

    float c[4][4][4];
#pragma unroll
    for (int i = 0; i < 4; i++)
#pragma unroll
        for (int j = 0; j < 4; j++)
#pragma unroll
            for (int q = 0; q < 4; q++) c[i][j][q] = 0.f;

    const int NT = DM / 32;
    ldB(0); stsB(0); issueA(0, 0);
    ldB(1); issueA(1, 1);

    for (int t = 0; t < NT; t++) {
        const int s = t & 1;
        cp_wait1();
        __syncthreads();
        const uint32_t Ao = aldmA + s * A_BUF_BYTES;
        const uint32_t Bo = aldmB + s * B_BUF_BYTES;
#pragma unroll
        for (int kk = 0; kk < 32; kk += 16) {
            uint32_t ra[4][4];
#pragma unroll
            for (int mt = 0; mt < 4; mt++)
                ldm_x4(ra[mt], Ao + (mt * 16 * ASTR_H + kk) * 2);
            uint32_t rb0[4], rb1[4];
            ldm_x4_t(rb0, Bo + (kk * BSTR_H) * 2);
            ldm_x4_t(rb1, Bo + (kk * BSTR_H + 16) * 2);
#pragma unroll
            for (int mt = 0; mt < 4; mt++) {
                mma_f16(c[mt][0], ra[mt], rb0);
                mma_f16(c[mt][1], ra[mt], rb0 + 2);
                mma_f16(c[mt][2], ra[mt], rb1);
                mma_f16(c[mt][3], ra[mt], rb1 + 2);
            }
        }
        __syncthreads();
        stsB(s ^ 1);                       // tile t+1 -> buf s^1
        const int tn = min(t + 2, NT - 1);
        ldB(tn);
        issueA(tn, s);
    }

    // ---- epilogue: bias + a*silu(g) -> g_acth (fp16, sorted rows) ----
    const float* b1e = b1 + (size_t)e * NH;
#pragma unroll
    for (int mt = 0; mt < 4; mt++) {
#pragma unroll
        for (int q = 0; q < 2; q++) {
            const float* ca = c[mt][2 * q];
            const float* cg = c[mt][2 * q + 1];
            const int acol = n0a + 8 * ((wn >> 4) + q) + 2 * tg;
            const float ba0 = b1e[acol],       ba1 = b1e[acol + 1];
            const float bg0 = b1e[DFF + acol], bg1 = b1e[DFF + acol + 1];
            const int r0 = wm + mt * 16 + g;
#pragma unroll
            for (int h = 0; h < 2; h++) {
                const int r = r0 + 8 * h;
                if (r < rowsv) {
                    float a0 = ca[2 * h] + ba0, a1 = ca[2 * h + 1] + ba1;
                    float g0 = cg[2 * h] + bg0, g1 = cg[2 * h + 1] + bg1;
                    float s0 = g0 / (1.f + expf(-g0));
                    float s1 = g1 / (1.f + expf(-g1));
                    *(__half2*)&g_acth[(size_t)(off + row0 + r) * DFF + acol] =
                        __floats2half2_rn(a0 * s0, a1 * s1);
                }
            }
        }
    }
}

// ---------------- GEMM2: act_sorted(fp16) @ W2 -> atomicAdd into out (split-K x2) ----
__global__ __launch_bounds__(256, 2)
void gemm2_mma(const float* __restrict__ W2, float* __restrict__ out) {
    const int e     = blockIdx.z & 15;
    const int split = blockIdx.z >> 4;
    const int off  = g_offsets[e];
    const int cnt  = g_offsets[e + 1] - off;
    const int row0 = blockIdx.y * 128;
    if (row0 >= cnt) return;
    const int n0 = blockIdx.x * 128;
    const int rowsv = min(128, cnt - row0);
    const int kbase = split * (DFF / 2);

    extern __shared__ char sm[];
    const uint32_t smb = (uint32_t)__cvta_generic_to_shared(sm);
    int* toks = (int*)(sm + SM_TOK_BASE);

    const int tid = threadIdx.x;
    const int wid = tid >> 5, lane = tid & 31;
    const int g = lane >> 2, tg = lane & 3;
    const int wm = (wid >> 2) * 64;
    const int wn = (wid & 3) * 32;

    if (tid < 128) toks[tid] = (tid < rowsv) ? g_perm[off + row0 + tid] : -1;

    const int arow_i = tid >> 1, ahalf = tid & 1;
    const bool avalid = (arow_i < rowsv);
    const __half* arow = avalid ? (g_acth + (size_t)(off + row0 + arow_i) * DFF + kbase) : g_acth;
    const int ab = avalid ? 16 : 0;
    const uint32_t aA = smb + (arow_i * ASTR_H + ahalf * 16) * 2;

    const int colc = (tid & 31) * 4;
    const int rowb = tid >> 5;
    const float* W2e = W2 + (size_t)e * DFF * DM + (size_t)kbase * DM + n0;
    const uint32_t aB = smb + SM_B_BASE + (rowb * BSTR_H + colc) * 2;

    float bre[16];
    auto ldB = [&](int t) {
        const int k0 = t * 32;
#pragma unroll
        for (int j = 0; j < 4; j++) {
            float4 v = *(const float4*)(W2e + (size_t)(k0 + rowb + 8 * j) * DM + colc);
            bre[4 * j] = v.x; bre[4 * j + 1] = v.y; bre[4 * j + 2] = v.z; bre[4 * j + 3] = v.w;
        }
    };
    auto stsB = [&](int s) {
        const uint32_t base = aB + s * B_BUF_BYTES;
#pragma unroll
        for (int j = 0; j < 4; j++)
            sts64(base + (8 * j * BSTR_H) * 2,
                  pack_h2(bre[4 * j], bre[4 * j + 1]),
                  pack_h2(bre[4 * j + 2], bre[4 * j + 3]));
    };
    auto issueA = [&](int t, int s) {
        const int k0 = t * 32 + ahalf * 16;
        cp16(aA + s * A_BUF_BYTES,      arow + k0,     ab);
        cp16(aA + s * A_BUF_BYTES + 16, arow + k0 + 8, ab);
        cp_commit();
    };

    const uint32_t aldmA = smb + ((wm + (lane & 15)) * ASTR_H + (lane >> 4) * 8) * 2;
    const int btr = (lane & 7) + 8 * ((lane >> 3) & 1);
    const int btc = 8 * (lane >> 4);
    const uint32_t aldmB = smb + SM_B_BASE + (btr * BSTR_H + wn + btc) * 2;

    float c[4][4][4];
#pragma unroll
    for (int i = 0; i < 4; i++)
#pragma unroll
        for (int j = 0; j < 4; j++)
#pragma unroll
            for (int q = 0; q < 4; q++) c[i][j][q] = 0.f;

    const int NT = (DFF / 2) / 32;
    ldB(0); stsB(0); issueA(0, 0);
    ldB(1); issueA(1, 1);

    for (int t = 0; t < NT; t++) {
        const int s = t & 1;
        cp_wait1();
        __syncthreads();
        const uint32_t Ao = aldmA + s * A_BUF_BYTES;
        const uint32_t Bo = aldmB + s * B_BUF_BYTES;
#pragma unroll
        for (int kk = 0; kk < 32; kk += 16) {
            uint32_t ra[4][4];
#pragma unroll
            for (int mt = 0; mt < 4; mt++)
                ldm_x4(ra[mt], Ao + (mt * 16 * ASTR_H + kk) * 2);
            uint32_t rb0[4], rb1[4];
            ldm_x4_t(rb0, Bo + (kk * BSTR_H) * 2);
            ldm_x4_t(rb1, Bo + (kk * BSTR_H + 16) * 2);
#pragma unroll
            for (int mt = 0; mt < 4; mt++) {
                mma_f16(c[mt][0], ra[mt], rb0);
                mma_f16(c[mt][1], ra[mt], rb0 + 2);
                mma_f16(c[mt][2], ra[mt], rb1);
                mma_f16(c[mt][3], ra[mt], rb1 + 2);
            }
        }
        __syncthreads();
        stsB(s ^ 1);
        const int tn = min(t + 2, NT - 1);
        ldB(tn);
        issueA(tn, s);
    }

    // ---- epilogue: atomic accumulate into out (bias pre-initialized) ----
#pragma unroll
    for (int mt = 0; mt < 4; mt++) {
        const int r0 = wm + mt * 16 + g;
#pragma unroll
        for (int h = 0; h < 2; h++) {
            const int r = r0 + 8 * h;
            if (r < rowsv) {
                const int tok = toks[r];
                float* drow = out + (size_t)tok * DM + n0 + wn;
#pragma unroll
                for (int nt = 0; nt < 4; nt++) {
                    atomicAdd(drow + 8 * nt + 2 * tg,     c[mt][nt][2 * h]);
                    atomicAdd(drow + 8 * nt + 2 * tg + 1, c[mt][nt][2 * h + 1]);
                }
            }
        }
    }
}

// ---------------- launch ----------------
extern "C" void kernel_launch(void* const* d_in, const int* in_sizes, int n_in,
                              void* d_out, int out_size) {
    const float* x   = (const float*)d_in[0];
    const float* W1  = (const float*)d_in[1];
    const float* b1  = (const float*)d_in[2];
    const float* W2  = (const float*)d_in[3];
    const float* b2  = (const float*)d_in[4];
    const float* Wga = (const float*)d_in[5];
    const float* bga = (const float*)d_in[6];
    const float* Wgb = (const float*)d_in[7];
    const float* bgb = (const float*)d_in[8];
    float* out = (float*)d_out;

    cudaFuncSetAttribute(gemm1_mma, cudaFuncAttributeMaxDynamicSharedMemorySize, SM_TOTAL);
    cudaFuncSetAttribute(gemm2_mma, cudaFuncAttributeMaxDynamicSharedMemorySize, SM_TOTAL);

    zero_kernel<<<1, 64>>>();
    gating_kernel<<<TT / 8, 256>>>(x, Wga, bga, Wgb, bgb);
    scan_kernel<<<1, 32>>>(out, out_size);
    scatter_kernel<<<TT / 256, 256>>>();
    cvt_x_kernel<<<TT * DM / 1024, 256>>>(x);
    init_out_kernel<<<TT * DM / 1024, 256>>>(b2, out);
    gemm1_mma<<<dim3(32, 16, NE), 256, SM_TOTAL>>>(W1, b1);
    gemm2_mma<<<dim3(8, 16, NE * 2), 256, SM_TOTAL>>>(W2, out);
}

// round 7
// speedup vs baseline: 1.7654x; 1.0419x over previous
#include <cuda_runtime.h>
#include <cuda_fp16.h>
#include <math.h>
#include <stdint.h>

// Problem constants
#define TT    2048
#define DM    1024
#define DFF   2048
#define NH    4096
#define NE    16
#define NAg   4
#define NBg   4

// ---------------- device scratch ----------------
__device__ int    g_eidx[TT];
__device__ int    g_counts[NE];
__device__ int    g_offsets[NE + 1];
__device__ int    g_pos[NE];
__device__ int    g_perm[TT];
__device__ float  g_probsum[NAg + NBg];
__device__ float  g_ohsum[NAg + NBg];
__device__ __half g_xh[(size_t)TT * DM];     // fp16 copy of x
__device__ __half g_acth[(size_t)TT * DFF];  // fp16 sorted activations

// ---------------- helpers ----------------
__device__ __forceinline__ void mma_f16(float c[4], const uint32_t a[4], const uint32_t b[2]) {
    asm volatile(
        "mma.sync.aligned.m16n8k16.row.col.f32.f16.f16.f32 "
        "{%0,%1,%2,%3}, {%4,%5,%6,%7}, {%8,%9}, {%0,%1,%2,%3};"
        : "+f"(c[0]), "+f"(c[1]), "+f"(c[2]), "+f"(c[3])
        : "r"(a[0]), "r"(a[1]), "r"(a[2]), "r"(a[3]), "r"(b[0]), "r"(b[1]));
}
__device__ __forceinline__ void ldm_x4(uint32_t r[4], uint32_t addr) {
    asm volatile("ldmatrix.sync.aligned.m8n8.x4.shared.b16 {%0,%1,%2,%3}, [%4];"
                 : "=r"(r[0]), "=r"(r[1]), "=r"(r[2]), "=r"(r[3]) : "r"(addr));
}
__device__ __forceinline__ void ldm_x4_t(uint32_t r[4], uint32_t addr) {
    asm volatile("ldmatrix.sync.aligned.m8n8.x4.trans.shared.b16 {%0,%1,%2,%3}, [%4];"
                 : "=r"(r[0]), "=r"(r[1]), "=r"(r[2]), "=r"(r[3]) : "r"(addr));
}
__device__ __forceinline__ uint32_t pack_h2(float lo, float hi) {
    __half2 h = __floats2half2_rn(lo, hi);
    return *(uint32_t*)&h;
}
__device__ __forceinline__ void sts64(uint32_t addr, uint32_t v0, uint32_t v1) {
    asm volatile("st.shared.v2.u32 [%0], {%1,%2};" :: "r"(addr), "r"(v0), "r"(v1) : "memory");
}
__device__ __forceinline__ void cp16(uint32_t dst, const void* src, int src_bytes) {
    asm volatile("cp.async.cg.shared.global [%0], [%1], 16, %2;"
                 :: "r"(dst), "l"(src), "r"(src_bytes));
}
__device__ __forceinline__ void cp_commit() { asm volatile("cp.async.commit_group;"); }
__device__ __forceinline__ void cp_wait1()  { asm volatile("cp.async.wait_group 1;"); }

// ---------------- small kernels ----------------
// cvt_x + zero fused (block 0 zeroes the gating accumulators)
__global__ void cvt_x_kernel(const float* __restrict__ x) {
    if (blockIdx.x == 0) {
        int t = threadIdx.x;
        if (t < NE) g_counts[t] = 0;
        if (t < NAg + NBg) { g_probsum[t] = 0.f; g_ohsum[t] = 0.f; }
    }
    int i = (blockIdx.x * blockDim.x + threadIdx.x) * 4;
    float4 v = *(const float4*)(x + i);
    __half2* dst = (__half2*)(g_xh + i);
    dst[0] = __floats2half2_rn(v.x, v.y);
    dst[1] = __floats2half2_rn(v.z, v.w);
}

__global__ void gating_kernel(const float* __restrict__ x,
                              const float* __restrict__ Wga, const float* __restrict__ bga,
                              const float* __restrict__ Wgb, const float* __restrict__ bgb) {
    int warp = (blockIdx.x * blockDim.x + threadIdx.x) >> 5;
    int lane = threadIdx.x & 31;
    if (warp >= TT) return;
    const float* xr = x + (size_t)warp * DM;

    float acc[8];
#pragma unroll
    for (int j = 0; j < 8; j++) acc[j] = 0.f;
    for (int k = lane; k < DM; k += 32) {
        float xv = xr[k];
#pragma unroll
        for (int j = 0; j < 4; j++) acc[j]     += xv * Wga[k * 4 + j];
#pragma unroll
        for (int j = 0; j < 4; j++) acc[4 + j] += xv * Wgb[k * 4 + j];
    }
#pragma unroll
    for (int off = 16; off > 0; off >>= 1)
#pragma unroll
        for (int j = 0; j < 8; j++)
            acc[j] += __shfl_xor_sync(0xFFFFFFFFu, acc[j], off);

    if (lane == 0) {
        float la[4], lb[4];
#pragma unroll
        for (int j = 0; j < 4; j++) { la[j] = acc[j] + bga[j]; lb[j] = acc[4 + j] + bgb[j]; }
        float ma = la[0]; int ia = 0;
#pragma unroll
        for (int j = 1; j < 4; j++) if (la[j] > ma) { ma = la[j]; ia = j; }
        float mb = lb[0]; int ib = 0;
#pragma unroll
        for (int j = 1; j < 4; j++) if (lb[j] > mb) { mb = lb[j]; ib = j; }
        float pa[4], pb[4], sa = 0.f, sb = 0.f;
#pragma unroll
        for (int j = 0; j < 4; j++) { pa[j] = expf(la[j] - ma); sa += pa[j]; }
#pragma unroll
        for (int j = 0; j < 4; j++) { pb[j] = expf(lb[j] - mb); sb += pb[j]; }
        float rsa = 1.f / sa, rsb = 1.f / sb;
        int e = ia * NBg + ib;
        g_eidx[warp] = e;
        atomicAdd(&g_counts[e], 1);
#pragma unroll
        for (int j = 0; j < 4; j++) {
            atomicAdd(&g_probsum[j],     pa[j] * rsa);
            atomicAdd(&g_probsum[4 + j], pb[j] * rsb);
        }
        atomicAdd(&g_ohsum[ia], 1.f);
        atomicAdd(&g_ohsum[4 + ib], 1.f);
    }
}

__global__ void scan_kernel(float* __restrict__ out, int out_size) {
    if (threadIdx.x == 0) {
        int off = 0;
        for (int e = 0; e < NE; e++) {
            g_offsets[e] = off;
            g_pos[e] = off;
            off += g_counts[e];
        }
        g_offsets[NE] = off;
        if (out_size > TT * DM) {
            const float invT = 1.f / (float)TT;
            float auxA = 0.f, auxB = 0.f;
            for (int j = 0; j < 4; j++) auxA += (g_probsum[j]     * invT) * (g_ohsum[j]     * invT);
            for (int j = 0; j < 4; j++) auxB += (g_probsum[4 + j] * invT) * (g_ohsum[4 + j] * invT);
            out[TT * DM] = (float)NAg * auxA + (float)NBg * auxB;
        }
    }
}

__global__ void scatter_kernel() {
    int t = blockIdx.x * blockDim.x + threadIdx.x;
    if (t >= TT) return;
    int e = g_eidx[t];
    int p = atomicAdd(&g_pos[e], 1);
    g_perm[p] = t;
}

// out[t][:] = b2[e_idx[t]][:]  (bias pre-init for split-K atomic accumulation)
__global__ void init_out_kernel(const float* __restrict__ b2, float* __restrict__ out) {
    int idx = blockIdx.x * blockDim.x + threadIdx.x;
    int t  = idx >> 8;
    int c4 = (idx & 255) * 4;
    int e = g_eidx[t];
    float4 bv = *(const float4*)(b2 + (size_t)e * DM + c4);
    *(float4*)(out + (size_t)t * DM + c4) = bv;
}

// =====================================================================
// GEMM geometry: CTA 128(M) x 128(outputs), BK=32, 8 warps (2M x 4N),
// warp tile 64x32, m16n8k16 fp16 HMMA, fp32 accum.
// A: fp16 smem TRIPLE buffer, stride 40 halves, cp.async 2-ahead.
// B: fp16 smem DOUBLE buffer, stride 136 halves (trans-ldmatrix
//    conflict-free); LDG.128 fp32 -> pack fp16 regs (2-ahead) -> STS.64
//    (1-ahead). ONE __syncthreads per tile.
// smem: A[3]@0 (3x10240=30720) | B[2]@30720 (2x8704) | toks@48128.
// total 48640 B -> 2 CTAs/SM.
// =====================================================================
#define ASTR_H 40
#define BSTR_H 136
#define A_BUF_BYTES 10240
#define B_BUF_BYTES 8704
#define SM_B_BASE   30720
#define SM_TOK_BASE 48128
#define SM_TOTAL    48640

// ---------------- GEMM1: x_sorted(fp16) @ W1 (+b1) -> SwiGLU -> g_acth ----------------
__global__ __launch_bounds__(256, 2)
void gemm1_mma(const float* __restrict__ W1, const float* __restrict__ b1) {
    const int e = blockIdx.z;
    const int off  = g_offsets[e];
    const int cnt  = g_offsets[e + 1] - off;
    const int row0 = blockIdx.y * 128;
    if (row0 >= cnt) return;
    const int n0a = blockIdx.x * 64;
    const int rowsv = min(128, cnt - row0);

    extern __shared__ char sm[];
    const uint32_t smb = (uint32_t)__cvta_generic_to_shared(sm);

    const int tid = threadIdx.x;
    const int wid = tid >> 5, lane = tid & 31;
    const int g = lane >> 2, tg = lane & 3;
    const int wm = (wid >> 2) * 64;
    const int wn = (wid & 3) * 32;

    // A loader: 2 threads per row, 32B each
    const int arow_i = tid >> 1, ahalf = tid & 1;
    const int atok = (arow_i < rowsv) ? g_perm[off + row0 + arow_i] : -1;
    const __half* arow = (atok >= 0) ? (g_xh + (size_t)atok * DM) : g_xh;
    const int ab = (atok >= 0) ? 16 : 0;
    const uint32_t aA = smb + (arow_i * ASTR_H + ahalf * 16) * 2;

    // B loader: fp32 LDG -> fp16 regs -> STS
    const int colc = (tid & 31) * 4;
    const int rowb = tid >> 5;
    const int pgrp = colc >> 4, wgrp = colc & 15;
    const int gcol = (wgrp < 8) ? (n0a + 8 * pgrp + wgrp)
                                : (DFF + n0a + 8 * pgrp + (wgrp - 8));
    const float* W1e = W1 + (size_t)e * DM * NH;
    const uint32_t aB = smb + SM_B_BASE + (rowb * BSTR_H + colc) * 2;

    uint32_t bh[8];   // 4 rows x 4 cols packed fp16
    auto ldB = [&](int t) {
        const int k0 = t * 32;
#pragma unroll
        for (int j = 0; j < 4; j++) {
            float4 v = *(const float4*)(W1e + (size_t)(k0 + rowb + 8 * j) * NH + gcol);
            bh[2 * j]     = pack_h2(v.x, v.y);
            bh[2 * j + 1] = pack_h2(v.z, v.w);
        }
    };
    auto stsB = [&](int s) {
        const uint32_t base = aB + s * B_BUF_BYTES;
#pragma unroll
        for (int j = 0; j < 4; j++)
            sts64(base + (8 * j * BSTR_H) * 2, bh[2 * j], bh[2 * j + 1]);
    };
    auto issueA = [&](int t, int s) {
        const int k0 = t * 32 + ahalf * 16;
        cp16(aA + s * A_BUF_BYTES,      arow + k0,     ab);
        cp16(aA + s * A_BUF_BYTES + 16, arow + k0 + 8, ab);
        cp_commit();
    };

    // ldmatrix bases
    const uint32_t aldmA = smb + ((wm + (lane & 15)) * ASTR_H + (lane >> 4) * 8) * 2;
    const int btr = (lane & 7) + 8 * ((lane >> 3) & 1);
    const int btc = 8 * (lane >> 4);
    const uint32_t aldmB = smb + SM_B_BASE + (btr * BSTR_H + wn + btc) * 2;

    float c[4][4][4];
#pragma unroll
    for (int i = 0; i < 4; i++)
#pragma unroll
        for (int j = 0; j < 4; j++)
#pragma unroll
            for (int q = 0; q < 4; q++) c[i][j][q] = 0.f;

    const int NT = DM / 32;
    ldB(0); stsB(0);            // B tile0 -> buf0
    ldB(1);                     // B tile1 staged in regs
    issueA(0, 0); issueA(1, 1); // A tiles 0,1 -> bufs 0,1

    int sA = 0;                 // A buffer index (t % 3)
    for (int t = 0; t < NT; t++) {
        const int sB = t & 1;
        cp_wait1();
        __syncthreads();
        // future producers (safe after the barrier; overlap with compute)
        if (t + 1 < NT) stsB(sB ^ 1);                 // B(t+1) regs -> smem
        const int tn = (t + 2 < NT) ? t + 2 : t;
        ldB(tn);                                      // B(t+2) -> regs
        int sA2 = sA + 2; if (sA2 >= 3) sA2 -= 3;
        issueA(tn, sA2);                              // A(t+2) -> buf (t+2)%3

        const uint32_t Ao = aldmA + sA * A_BUF_BYTES;
        const uint32_t Bo = aldmB + sB * B_BUF_BYTES;
#pragma unroll
        for (int kk = 0; kk < 32; kk += 16) {
            uint32_t ra[4][4];
#pragma unroll
            for (int mt = 0; mt < 4; mt++)
                ldm_x4(ra[mt], Ao + (mt * 16 * ASTR_H + kk) * 2);
            uint32_t rb0[4], rb1[4];
            ldm_x4_t(rb0, Bo + (kk * BSTR_H) * 2);
            ldm_x4_t(rb1, Bo + (kk * BSTR_H + 16) * 2);
#pragma unroll
            for (int mt = 0; mt < 4; mt++) {
                mma_f16(c[mt][0], ra[mt], rb0);
                mma_f16(c[mt][1], ra[mt], rb0 + 2);
                mma_f16(c[mt][2], ra[mt], rb1);
                mma_f16(c[mt][3], ra[mt], rb1 + 2);
            }
        }
        if (++sA == 3) sA = 0;
    }

    // ---- epilogue: bias + a*silu(g) -> g_acth (fp16, sorted rows) ----
    const float* b1e = b1 + (size_t)e * NH;
#pragma unroll
    for (int mt = 0; mt < 4; mt++) {
#pragma unroll
        for (int q = 0; q < 2; q++) {
            const float* ca = c[mt][2 * q];
            const float* cg = c[mt][2 * q + 1];
            const int acol = n0a + 8 * ((wn >> 4) + q) + 2 * tg;
            const float ba0 = b1e[acol],       ba1 = b1e[acol + 1];
            const float bg0 = b1e[DFF + acol], bg1 = b1e[DFF + acol + 1];
            const int r0 = wm + mt * 16 + g;
#pragma unroll
            for (int h = 0; h < 2; h++) {
                const int r = r0 + 8 * h;
                if (r < rowsv) {
                    float a0 = ca[2 * h] + ba0, a1 = ca[2 * h + 1] + ba1;
                    float g0 = cg[2 * h] + bg0, g1 = cg[2 * h + 1] + bg1;
                    float s0 = g0 / (1.f + expf(-g0));
                    float s1 = g1 / (1.f + expf(-g1));
                    *(__half2*)&g_acth[(size_t)(off + row0 + r) * DFF + acol] =
                        __floats2half2_rn(a0 * s0, a1 * s1);
                }
            }
        }
    }
}

// ---------------- GEMM2: act_sorted(fp16) @ W2 -> atomicAdd into out (split-K x2) ----
__global__ __launch_bounds__(256, 2)
void gemm2_mma(const float* __restrict__ W2, float* __restrict__ out) {
    const int e     = blockIdx.z & 15;
    const int split = blockIdx.z >> 4;
    const int off  = g_offsets[e];
    const int cnt  = g_offsets[e + 1] - off;
    const int row0 = blockIdx.y * 128;
    if (row0 >= cnt) return;
    const int n0 = blockIdx.x * 128;
    const int rowsv = min(128, cnt - row0);
    const int kbase = split * (DFF / 2);

    extern __shared__ char sm[];
    const uint32_t smb = (uint32_t)__cvta_generic_to_shared(sm);
    int* toks = (int*)(sm + SM_TOK_BASE);

    const int tid = threadIdx.x;
    const int wid = tid >> 5, lane = tid & 31;
    const int g = lane >> 2, tg = lane & 3;
    const int wm = (wid >> 2) * 64;
    const int wn = (wid & 3) * 32;

    if (tid < 128) toks[tid] = (tid < rowsv) ? g_perm[off + row0 + tid] : -1;

    const int arow_i = tid >> 1, ahalf = tid & 1;
    const bool avalid = (arow_i < rowsv);
    const __half* arow = avalid ? (g_acth + (size_t)(off + row0 + arow_i) * DFF + kbase) : g_acth;
    const int ab = avalid ? 16 : 0;
    const uint32_t aA = smb + (arow_i * ASTR_H + ahalf * 16) * 2;

    const int colc = (tid & 31) * 4;
    const int rowb = tid >> 5;
    const float* W2e = W2 + (size_t)e * DFF * DM + (size_t)kbase * DM + n0;
    const uint32_t aB = smb + SM_B_BASE + (rowb * BSTR_H + colc) * 2;

    uint32_t bh[8];
    auto ldB = [&](int t) {
        const int k0 = t * 32;
#pragma unroll
        for (int j = 0; j < 4; j++) {
            float4 v = *(const float4*)(W2e + (size_t)(k0 + rowb + 8 * j) * DM + colc);
            bh[2 * j]     = pack_h2(v.x, v.y);
            bh[2 * j + 1] = pack_h2(v.z, v.w);
        }
    };
    auto stsB = [&](int s) {
        const uint32_t base = aB + s * B_BUF_BYTES;
#pragma unroll
        for (int j = 0; j < 4; j++)
            sts64(base + (8 * j * BSTR_H) * 2, bh[2 * j], bh[2 * j + 1]);
    };
    auto issueA = [&](int t, int s) {
        const int k0 = t * 32 + ahalf * 16;
        cp16(aA + s * A_BUF_BYTES,      arow + k0,     ab);
        cp16(aA + s * A_BUF_BYTES + 16, arow + k0 + 8, ab);
        cp_commit();
    };

    const uint32_t aldmA = smb + ((wm + (lane & 15)) * ASTR_H + (lane >> 4) * 8) * 2;
    const int btr = (lane & 7) + 8 * ((lane >> 3) & 1);
    const int btc = 8 * (lane >> 4);
    const uint32_t aldmB = smb + SM_B_BASE + (btr * BSTR_H + wn + btc) * 2;

    float c[4][4][4];
#pragma unroll
    for (int i = 0; i < 4; i++)
#pragma unroll
        for (int j = 0; j < 4; j++)
#pragma unroll
            for (int q = 0; q < 4; q++) c[i][j][q] = 0.f;

    const int NT = (DFF / 2) / 32;
    ldB(0); stsB(0);
    ldB(1);
    issueA(0, 0); issueA(1, 1);

    int sA = 0;
    for (int t = 0; t < NT; t++) {
        const int sB = t & 1;
        cp_wait1();
        __syncthreads();
        if (t + 1 < NT) stsB(sB ^ 1);
        const int tn = (t + 2 < NT) ? t + 2 : t;
        ldB(tn);
        int sA2 = sA + 2; if (sA2 >= 3) sA2 -= 3;
        issueA(tn, sA2);

        const uint32_t Ao = aldmA + sA * A_BUF_BYTES;
        const uint32_t Bo = aldmB + sB * B_BUF_BYTES;
#pragma unroll
        for (int kk = 0; kk < 32; kk += 16) {
            uint32_t ra[4][4];
#pragma unroll
            for (int mt = 0; mt < 4; mt++)
                ldm_x4(ra[mt], Ao + (mt * 16 * ASTR_H + kk) * 2);
            uint32_t rb0[4], rb1[4];
            ldm_x4_t(rb0, Bo + (kk * BSTR_H) * 2);
            ldm_x4_t(rb1, Bo + (kk * BSTR_H + 16) * 2);
#pragma unroll
            for (int mt = 0; mt < 4; mt++) {
                mma_f16(c[mt][0], ra[mt], rb0);
                mma_f16(c[mt][1], ra[mt], rb0 + 2);
                mma_f16(c[mt][2], ra[mt], rb1);
                mma_f16(c[mt][3], ra[mt], rb1 + 2);
            }
        }
        if (++sA == 3) sA = 0;
    }

    // ---- epilogue: atomic accumulate into out (bias pre-initialized) ----
#pragma unroll
    for (int mt = 0; mt < 4; mt++) {
        const int r0 = wm + mt * 16 + g;
#pragma unroll
        for (int h = 0; h < 2; h++) {
            const int r = r0 + 8 * h;
            if (r < rowsv) {
                const int tok = toks[r];
                float* drow = out + (size_t)tok * DM + n0 + wn;
#pragma unroll
                for (int nt = 0; nt < 4; nt++) {
                    atomicAdd(drow + 8 * nt + 2 * tg,     c[mt][nt][2 * h]);
                    atomicAdd(drow + 8 * nt + 2 * tg + 1, c[mt][nt][2 * h + 1]);
                }
            }
        }
    }
}

// ---------------- launch ----------------
extern "C" void kernel_launch(void* const* d_in, const int* in_sizes, int n_in,
                              void* d_out, int out_size) {
    const float* x   = (const float*)d_in[0];
    const float* W1  = (const float*)d_in[1];
    const float* b1  = (const float*)d_in[2];
    const float* W2  = (const float*)d_in[3];
    const float* b2  = (const float*)d_in[4];
    const float* Wga = (const float*)d_in[5];
    const float* bga = (const float*)d_in[6];
    const float* Wgb = (const float*)d_in[7];
    const float* bgb = (const float*)d_in[8];
    float* out = (float*)d_out;

    cudaFuncSetAttribute(gemm1_mma, cudaFuncAttributeMaxDynamicSharedMemorySize, SM_TOTAL);
    cudaFuncSetAttribute(gemm2_mma, cudaFuncAttributeMaxDynamicSharedMemorySize, SM_TOTAL);

    cvt_x_kernel<<<TT * DM / 1024, 256>>>(x);
    gating_kernel<<<TT / 8, 256>>>(x, Wga, bga, Wgb, bgb);
    scan_kernel<<<1, 32>>>(out, out_size);
    scatter_kernel<<<TT / 256, 256>>>();
    init_out_kernel<<<TT * DM / 1024, 256>>>(b2, out);
    gemm1_mma<<<dim3(32, 16, NE), 256, SM_TOTAL>>>(W1, b1);
    gemm2_mma<<<dim3(8, 16, NE * 2), 256, SM_TOTAL>>>(W2, out);
}